// round 1
// baseline (speedup 1.0000x reference)
#include <cuda_runtime.h>
#include <math.h>

// Problem constants
#define DM   1024          // model dim
#define SEQ  1024
#define BATCH 4
#define NTOK (BATCH*SEQ)   // 4096 tokens
#define HIDN 4096
#define NH   16
#define DHD  64

// ---------------------------------------------------------------------------
// Scratch (device globals; no allocation anywhere)
// ---------------------------------------------------------------------------
__device__ float g_Wp[3][DM*DM];        // packed Q/K/V weights  (12 MB)
__device__ float g_Q[NTOK*DM];
__device__ float g_K[NTOK*DM];
__device__ float g_V[NTOK*DM];
__device__ float g_Attn[NTOK*DM];
__device__ float g_Tmp[NTOK*DM];
__device__ float g_X1[NTOK*DM];
__device__ float g_X2[NTOK*DM];
__device__ float g_Hid[NTOK*HIDN];      // 64 MB

// ---------------------------------------------------------------------------
// Pack per-head weight [H, D, DH] -> standard row-major [D, H*DH]
// Wp[d][h*64+e] = W[h][d][e]
// ---------------------------------------------------------------------------
__global__ void pack_w_kernel(const float* __restrict__ W, float* __restrict__ Wp) {
    int idx = blockIdx.x * 256 + threadIdx.x;      // over DM*DM
    int n = idx & (DM - 1);
    int d = idx >> 10;
    int h = n >> 6, e = n & 63;
    Wp[idx] = W[h * (DM * DHD) + d * DHD + e];
}

// ---------------------------------------------------------------------------
// SGEMM: C[M,N] = A[M,K] @ B[K,N] + bias[N]   (optional ReLU)
// 128x128 block tile, Kt=8, 256 threads, 8x8 per thread.
// All dims are multiples of 128 here; no bounds checks.
// ---------------------------------------------------------------------------
template<bool RELU>
__global__ void __launch_bounds__(256) sgemm_kernel(
    const float* __restrict__ A, const float* __restrict__ B,
    const float* __restrict__ bias, float* __restrict__ C,
    int M, int N, int K)
{
    __shared__ float As[8][128];
    __shared__ float Bs[8][128];

    int tid = threadIdx.x;
    int bm = blockIdx.y * 128;
    int bn = blockIdx.x * 128;
    int tx = tid & 15, ty = tid >> 4;

    float acc[8][8];
#pragma unroll
    for (int i = 0; i < 8; i++)
#pragma unroll
        for (int j = 0; j < 8; j++) acc[i][j] = 0.f;

    int arow = tid >> 1;            // 0..127
    int acol = (tid & 1) * 4;       // 0 or 4
    int brow = tid >> 5;            // 0..7
    int bcol = (tid & 31) * 4;      // 0..124

    for (int k0 = 0; k0 < K; k0 += 8) {
        float4 av = *(const float4*)&A[(size_t)(bm + arow) * K + k0 + acol];
        float4 bv = *(const float4*)&B[(size_t)(k0 + brow) * N + bn + bcol];
        __syncthreads();
        As[acol + 0][arow] = av.x;
        As[acol + 1][arow] = av.y;
        As[acol + 2][arow] = av.z;
        As[acol + 3][arow] = av.w;
        *(float4*)&Bs[brow][bcol] = bv;
        __syncthreads();
#pragma unroll
        for (int kk = 0; kk < 8; kk++) {
            float4 a0 = *(const float4*)&As[kk][ty * 8];
            float4 a1 = *(const float4*)&As[kk][ty * 8 + 4];
            float4 b0 = *(const float4*)&Bs[kk][tx * 8];
            float4 b1 = *(const float4*)&Bs[kk][tx * 8 + 4];
            float a[8] = {a0.x, a0.y, a0.z, a0.w, a1.x, a1.y, a1.z, a1.w};
            float b[8] = {b0.x, b0.y, b0.z, b0.w, b1.x, b1.y, b1.z, b1.w};
#pragma unroll
            for (int i = 0; i < 8; i++)
#pragma unroll
                for (int j = 0; j < 8; j++)
                    acc[i][j] += a[i] * b[j];
        }
    }

#pragma unroll
    for (int i = 0; i < 8; i++) {
        int row = bm + ty * 8 + i;
#pragma unroll
        for (int j = 0; j < 8; j += 4) {
            int col = bn + tx * 8 + j;
            float4 v;
            v.x = acc[i][j + 0] + bias[col + 0];
            v.y = acc[i][j + 1] + bias[col + 1];
            v.z = acc[i][j + 2] + bias[col + 2];
            v.w = acc[i][j + 3] + bias[col + 3];
            if (RELU) {
                v.x = fmaxf(v.x, 0.f); v.y = fmaxf(v.y, 0.f);
                v.z = fmaxf(v.z, 0.f); v.w = fmaxf(v.w, 0.f);
            }
            *(float4*)&C[(size_t)row * N + col] = v;
        }
    }
}

// ---------------------------------------------------------------------------
// Flash attention (fp32, online softmax).
// Q,K,V layout: [B*S, H*DH] (token-major, head slice at h*64).
// Grid: (S/64, H, B). Block: 256 threads.
// Thread (r = tid>>2, c4 = tid&3): owns query row r; computes 16 interleaved
// score columns k = j*4+c4; after exchanging P through shared, owns 16 output
// dims t in {c4*4..c4*4+3} (float4 granularity).
// ---------------------------------------------------------------------------
#define ATTN_SMEM (17408 + 17408 + 16384 + 17408)   // Qs + Ks + Vs + Ps = 68608 B

__global__ void __launch_bounds__(256, 2) attn_kernel(
    const float* __restrict__ Qg, const float* __restrict__ Kg,
    const float* __restrict__ Vg, float* __restrict__ Og)
{
    extern __shared__ float smem[];
    float4* Qs = (float4*)smem;            // [64][17]  (pad -> conflict free)
    float4* Ks = Qs + 64 * 17;             // [64][17]
    float4* Vs = Ks + 64 * 17;             // [64][16]
    float*  Ps = (float*)(Vs + 64 * 16);   // [64][68]  (pad 68 -> conflict free)

    int tid = threadIdx.x;
    int qt = blockIdx.x, h = blockIdx.y, b = blockIdx.z;
    int r = tid >> 2, c4 = tid & 3;

    const float* qbase = Qg + (size_t)(b * SEQ + qt * 64) * DM + h * DHD;
#pragma unroll
    for (int i = 0; i < 4; i++) {
        int id = tid + i * 256;
        int row = id >> 4, col = id & 15;
        Qs[row * 17 + col] = *(const float4*)(qbase + (size_t)row * DM + col * 4);
    }

    float m_prev = -1e30f, l = 0.f;
    float4 Oa[4];
#pragma unroll
    for (int i = 0; i < 4; i++) Oa[i] = make_float4(0.f, 0.f, 0.f, 0.f);

    for (int kt = 0; kt < 16; kt++) {
        const float* kbase = Kg + (size_t)(b * SEQ + kt * 64) * DM + h * DHD;
        const float* vbase = Vg + (size_t)(b * SEQ + kt * 64) * DM + h * DHD;
        __syncthreads();   // prior iteration's reads of Ks/Vs/Ps done
#pragma unroll
        for (int i = 0; i < 4; i++) {
            int id = tid + i * 256;
            int row = id >> 4, col = id & 15;
            Ks[row * 17 + col] = *(const float4*)(kbase + (size_t)row * DM + col * 4);
            Vs[row * 16 + col] = *(const float4*)(vbase + (size_t)row * DM + col * 4);
        }
        __syncthreads();

        // scores: s[j] = Q[r,:] . K[j*4+c4,:]
        float s[16];
#pragma unroll
        for (int j = 0; j < 16; j++) s[j] = 0.f;
#pragma unroll
        for (int e = 0; e < 16; e++) {
            float4 q = Qs[r * 17 + e];
#pragma unroll
            for (int j = 0; j < 16; j++) {
                float4 k4 = Ks[(j * 4 + c4) * 17 + e];
                s[j] += q.x * k4.x + q.y * k4.y + q.z * k4.z + q.w * k4.w;
            }
        }
        float mt = -1e30f;
#pragma unroll
        for (int j = 0; j < 16; j++) { s[j] *= 0.125f; mt = fmaxf(mt, s[j]); }
        mt = fmaxf(mt, __shfl_xor_sync(0xffffffffu, mt, 1));
        mt = fmaxf(mt, __shfl_xor_sync(0xffffffffu, mt, 2));
        float m_new = fmaxf(m_prev, mt);

        float p[16], lloc = 0.f;
#pragma unroll
        for (int j = 0; j < 16; j++) { p[j] = __expf(s[j] - m_new); lloc += p[j]; }
        lloc += __shfl_xor_sync(0xffffffffu, lloc, 1);
        lloc += __shfl_xor_sync(0xffffffffu, lloc, 2);
        float alpha = __expf(m_prev - m_new);
        l = l * alpha + lloc;
#pragma unroll
        for (int i = 0; i < 4; i++) {
            Oa[i].x *= alpha; Oa[i].y *= alpha; Oa[i].z *= alpha; Oa[i].w *= alpha;
        }

        // exchange P so PV is conflict-free and no cross-lane O reduce is needed
#pragma unroll
        for (int j = 0; j < 16; j++) Ps[r * 68 + j * 4 + c4] = p[j];
        __syncthreads();

#pragma unroll
        for (int k = 0; k < 64; k++) {
            float pv = Ps[r * 68 + k];
#pragma unroll
            for (int i = 0; i < 4; i++) {
                float4 v = Vs[k * 16 + c4 * 4 + i];
                Oa[i].x += pv * v.x; Oa[i].y += pv * v.y;
                Oa[i].z += pv * v.z; Oa[i].w += pv * v.w;
            }
        }
        m_prev = m_new;
    }

    float inv = 1.f / l;
    float4* obase = (float4*)(Og + (size_t)(b * SEQ + qt * 64 + r) * DM + h * DHD);
#pragma unroll
    for (int i = 0; i < 4; i++) {
        float4 v = Oa[i];
        v.x *= inv; v.y *= inv; v.z *= inv; v.w *= inv;
        obase[c4 * 4 + i] = v;
    }
}

// ---------------------------------------------------------------------------
// Fused residual + LayerNorm: out[row] = LN(a[row] + b[row]) * g + beta
// One block (256 threads) per row of 1024.
// ---------------------------------------------------------------------------
__global__ void __launch_bounds__(256) ln_kernel(
    const float* __restrict__ Xa, const float* __restrict__ Xb,
    const float* __restrict__ g, const float* __restrict__ beta,
    float* __restrict__ out)
{
    int row = blockIdx.x;
    const float* a = Xa + (size_t)row * DM;
    const float* b = Xb + (size_t)row * DM;
    float vloc[4];
    float s = 0.f, ss = 0.f;
#pragma unroll
    for (int k = 0; k < 4; k++) {
        int i = threadIdx.x + k * 256;
        float v = a[i] + b[i];
        vloc[k] = v; s += v; ss += v * v;
    }
#pragma unroll
    for (int o = 16; o > 0; o >>= 1) {
        s  += __shfl_xor_sync(0xffffffffu, s, o);
        ss += __shfl_xor_sync(0xffffffffu, ss, o);
    }
    __shared__ float red[16];
    __shared__ float mu_s, rstd_s;
    int wid = threadIdx.x >> 5, lid = threadIdx.x & 31;
    if (lid == 0) { red[wid] = s; red[8 + wid] = ss; }
    __syncthreads();
    if (threadIdx.x == 0) {
        float S = 0.f, SS = 0.f;
        for (int i = 0; i < 8; i++) { S += red[i]; SS += red[8 + i]; }
        float mu = S * (1.f / DM);
        float var = SS * (1.f / DM) - mu * mu;
        mu_s = mu;
        rstd_s = rsqrtf(var + 1e-5f);
    }
    __syncthreads();
    float mu = mu_s, rstd = rstd_s;
    float* o = out + (size_t)row * DM;
#pragma unroll
    for (int k = 0; k < 4; k++) {
        int i = threadIdx.x + k * 256;
        o[i] = (vloc[k] - mu) * rstd * g[i] + beta[i];
    }
}

// ---------------------------------------------------------------------------
// Launch
// ---------------------------------------------------------------------------
extern "C" void kernel_launch(void* const* d_in, const int* in_sizes, int n_in,
                              void* d_out, int out_size)
{
    const float* q_in = (const float*)d_in[0];
    const float* mA   = (const float*)d_in[1];
    const float* mB   = (const float*)d_in[2];
    const float* Wq1 = (const float*)d_in[3];  const float* bq1 = (const float*)d_in[4];
    const float* Wk1 = (const float*)d_in[5];  const float* bk1 = (const float*)d_in[6];
    const float* Wv1 = (const float*)d_in[7];  const float* bv1 = (const float*)d_in[8];
    const float* Wo1 = (const float*)d_in[9];  const float* bo1 = (const float*)d_in[10];
    const float* Wq2 = (const float*)d_in[11]; const float* bq2 = (const float*)d_in[12];
    const float* Wk2 = (const float*)d_in[13]; const float* bk2 = (const float*)d_in[14];
    const float* Wv2 = (const float*)d_in[15]; const float* bv2 = (const float*)d_in[16];
    const float* Wo2 = (const float*)d_in[17]; const float* bo2 = (const float*)d_in[18];
    const float* W1  = (const float*)d_in[19]; const float* b1  = (const float*)d_in[20];
    const float* W2  = (const float*)d_in[21]; const float* b2  = (const float*)d_in[22];
    const float* g1  = (const float*)d_in[23]; const float* be1 = (const float*)d_in[24];
    const float* g2  = (const float*)d_in[25]; const float* be2 = (const float*)d_in[26];
    const float* g3  = (const float*)d_in[27]; const float* be3 = (const float*)d_in[28];
    float* out = (float*)d_out;

    float *pWp, *pQ, *pK, *pV, *pAttn, *pTmp, *pX1, *pX2, *pHid;
    cudaGetSymbolAddress((void**)&pWp,   g_Wp);
    cudaGetSymbolAddress((void**)&pQ,    g_Q);
    cudaGetSymbolAddress((void**)&pK,    g_K);
    cudaGetSymbolAddress((void**)&pV,    g_V);
    cudaGetSymbolAddress((void**)&pAttn, g_Attn);
    cudaGetSymbolAddress((void**)&pTmp,  g_Tmp);
    cudaGetSymbolAddress((void**)&pX1,   g_X1);
    cudaGetSymbolAddress((void**)&pX2,   g_X2);
    cudaGetSymbolAddress((void**)&pHid,  g_Hid);
    float* pW0 = pWp;
    float* pW1p = pWp + DM * DM;
    float* pW2p = pWp + 2 * DM * DM;

    cudaFuncSetAttribute(attn_kernel, cudaFuncAttributeMaxDynamicSharedMemorySize, ATTN_SMEM);

    const dim3 blk(256);
    const dim3 gPack(DM * DM / 256);
    const dim3 gGemm1k(DM / 128, NTOK / 128);        // N=1024
    const dim3 gGemmFF1(HIDN / 128, NTOK / 128);     // N=4096
    const dim3 gAttn(SEQ / 64, NH, BATCH);
    const dim3 gLN(NTOK);

    // ---- Attention block 1: Q from query, K/V from modality_A ----
    pack_w_kernel<<<gPack, blk>>>(Wq1, pW0);
    pack_w_kernel<<<gPack, blk>>>(Wk1, pW1p);
    pack_w_kernel<<<gPack, blk>>>(Wv1, pW2p);
    sgemm_kernel<false><<<gGemm1k, blk>>>(q_in, pW0,  bq1, pQ, NTOK, DM, DM);
    sgemm_kernel<false><<<gGemm1k, blk>>>(mA,   pW1p, bk1, pK, NTOK, DM, DM);
    sgemm_kernel<false><<<gGemm1k, blk>>>(mA,   pW2p, bv1, pV, NTOK, DM, DM);
    attn_kernel<<<gAttn, blk, ATTN_SMEM>>>(pQ, pK, pV, pAttn);
    sgemm_kernel<false><<<gGemm1k, blk>>>(pAttn, Wo1, bo1, pTmp, NTOK, DM, DM);
    ln_kernel<<<gLN, blk>>>(q_in, pTmp, g1, be1, pX1);

    // ---- Attention block 2: Q from x1, K/V from modality_B ----
    pack_w_kernel<<<gPack, blk>>>(Wq2, pW0);
    pack_w_kernel<<<gPack, blk>>>(Wk2, pW1p);
    pack_w_kernel<<<gPack, blk>>>(Wv2, pW2p);
    sgemm_kernel<false><<<gGemm1k, blk>>>(pX1, pW0,  bq2, pQ, NTOK, DM, DM);
    sgemm_kernel<false><<<gGemm1k, blk>>>(mB,  pW1p, bk2, pK, NTOK, DM, DM);
    sgemm_kernel<false><<<gGemm1k, blk>>>(mB,  pW2p, bv2, pV, NTOK, DM, DM);
    attn_kernel<<<gAttn, blk, ATTN_SMEM>>>(pQ, pK, pV, pAttn);
    sgemm_kernel<false><<<gGemm1k, blk>>>(pAttn, Wo2, bo2, pTmp, NTOK, DM, DM);
    ln_kernel<<<gLN, blk>>>(pX1, pTmp, g2, be2, pX2);

    // ---- FFN ----
    sgemm_kernel<true><<<gGemmFF1, blk>>>(pX2, W1, b1, pHid, NTOK, HIDN, DM);
    sgemm_kernel<false><<<gGemm1k, blk>>>(pHid, W2, b2, pTmp, NTOK, DM, HIDN);
    ln_kernel<<<gLN, blk>>>(pX2, pTmp, g3, be3, out);
}

// round 3
// speedup vs baseline: 1.4546x; 1.4546x over previous
#include <cuda_runtime.h>
#include <math.h>
#include <stdint.h>

// Problem constants
#define DM   1024          // model dim
#define SEQ  1024
#define BATCH 4
#define NTOK (BATCH*SEQ)   // 4096 tokens
#define HIDN 4096
#define NH   16
#define DHD  64

// ---------------------------------------------------------------------------
// Scratch (device globals; no allocation anywhere)
// ---------------------------------------------------------------------------
__device__ float g_Wp[3][DM*DM];        // packed Q/K/V weights  (12 MB)
__device__ float g_Q[NTOK*DM];
__device__ float g_K[NTOK*DM];
__device__ float g_V[NTOK*DM];
__device__ float g_Attn[NTOK*DM];
__device__ float g_Tmp[NTOK*DM];
__device__ float g_X1[NTOK*DM];
__device__ float g_X2[NTOK*DM];
__device__ float g_Hid[NTOK*HIDN];      // 64 MB

// ---------------------------------------------------------------------------
// Pack per-head weight [H, D, DH] -> standard row-major [D, H*DH]
// ---------------------------------------------------------------------------
__global__ void pack_w_kernel(const float* __restrict__ W, float* __restrict__ Wp) {
    int idx = blockIdx.x * 256 + threadIdx.x;      // over DM*DM
    int n = idx & (DM - 1);
    int d = idx >> 10;
    int h = n >> 6, e = n & 63;
    Wp[idx] = W[h * (DM * DHD) + d * DHD + e];
}

// ---------------------------------------------------------------------------
// TF32 tensor-core GEMM: C[M,N] = A[M,K] @ B[K,N] + bias[N] (optional ReLU)
// 128x128 tile, BK=16, 256 threads (8 warps, 2x4), warp tile 64x32.
// mma.sync.aligned.m16n8k8.row.col.f32.tf32.tf32.f32
// ---------------------------------------------------------------------------
#define BM 128
#define BN 128
#define BK 16
#define SA 20    // As row stride (floats)
#define SB 136   // Bs row stride (floats)

__device__ __forceinline__ uint32_t to_tf32(float x) {
    uint32_t y;
    asm("cvt.rna.tf32.f32 %0, %1;" : "=r"(y) : "f"(x));
    return y;
}

__device__ __forceinline__ void mma_tf32(
    float& d0, float& d1, float& d2, float& d3,
    uint32_t a0, uint32_t a1, uint32_t a2, uint32_t a3,
    uint32_t b0, uint32_t b1)
{
    asm volatile(
        "mma.sync.aligned.m16n8k8.row.col.f32.tf32.tf32.f32 "
        "{%0,%1,%2,%3}, {%4,%5,%6,%7}, {%8,%9}, {%0,%1,%2,%3};"
        : "+f"(d0), "+f"(d1), "+f"(d2), "+f"(d3)
        : "r"(a0), "r"(a1), "r"(a2), "r"(a3), "r"(b0), "r"(b1));
}

__device__ __forceinline__ uint4 cvt4(float4 v) {
    uint4 u;
    u.x = to_tf32(v.x); u.y = to_tf32(v.y);
    u.z = to_tf32(v.z); u.w = to_tf32(v.w);
    return u;
}

template<bool RELU>
__global__ void __launch_bounds__(256) tc_gemm_kernel(
    const float* __restrict__ A, const float* __restrict__ B,
    const float* __restrict__ bias, float* __restrict__ C,
    int M, int N, int K)
{
    __shared__ uint32_t As[2][BM * SA];   // [m][k], stride 20
    __shared__ uint32_t Bs[2][BK * SB];   // [k][n], stride 136

    int tid  = threadIdx.x;
    int wid  = tid >> 5, lane = tid & 31;
    int gid  = lane >> 2;              // 0..7
    int tig  = lane & 3;               // 0..3
    int wm   = (wid >> 2) * 64;        // warp m offset (0 or 64)
    int wn   = (wid & 3) * 32;         // warp n offset (0..96)

    int bm = blockIdx.y * BM;
    int bn = blockIdx.x * BN;

    // global load assignments
    int ar = tid >> 1;                 // A row 0..127
    int ac = (tid & 1) * 8;            // A col base {0,8}
    int br = tid >> 5;                 // B row 0..7 (second at +8)
    int bc = (tid & 31) * 4;           // B col 0..124

    const float* Aptr = A + (size_t)(bm + ar) * K + ac;
    const float* Bptr = B + (size_t)br * N + bn + bc;

    float4 a0v = *(const float4*)(Aptr);
    float4 a1v = *(const float4*)(Aptr + 4);
    float4 b0v = *(const float4*)(Bptr);
    float4 b1v = *(const float4*)(Bptr + (size_t)8 * N);

    float acc[4][4][4];
#pragma unroll
    for (int i = 0; i < 4; i++)
#pragma unroll
        for (int j = 0; j < 4; j++)
#pragma unroll
            for (int c = 0; c < 4; c++) acc[i][j][c] = 0.f;

    // store tile 0 (tf32-rounded)
    {
        uint32_t* ad = &As[0][ar * SA + ac];
        *(uint4*)(ad)     = cvt4(a0v);
        *(uint4*)(ad + 4) = cvt4(a1v);
        uint32_t* bd = &Bs[0][br * SB + bc];
        *(uint4*)(bd)          = cvt4(b0v);
        *(uint4*)(bd + 8 * SB) = cvt4(b1v);
    }
    __syncthreads();

    int nk = K / BK;
    int buf = 0;

    for (int it = 0; it < nk; ++it) {
        if (it + 1 < nk) {
            const float* An = Aptr + (it + 1) * BK;
            const float* Bn = Bptr + (size_t)(it + 1) * BK * N;
            a0v = *(const float4*)(An);
            a1v = *(const float4*)(An + 4);
            b0v = *(const float4*)(Bn);
            b1v = *(const float4*)(Bn + (size_t)8 * N);
        }

#pragma unroll
        for (int ks = 0; ks < 2; ks++) {
            int k0 = ks * 8;
            uint32_t afr[4][4];
            uint32_t bfr[4][2];
#pragma unroll
            for (int mt = 0; mt < 4; mt++) {
                const uint32_t* ap = &As[buf][(wm + mt * 16 + gid) * SA + k0 + tig];
                afr[mt][0] = ap[0];
                afr[mt][1] = ap[8 * SA];
                afr[mt][2] = ap[4];
                afr[mt][3] = ap[8 * SA + 4];
            }
#pragma unroll
            for (int nt = 0; nt < 4; nt++) {
                const uint32_t* bp = &Bs[buf][(k0 + tig) * SB + wn + nt * 8 + gid];
                bfr[nt][0] = bp[0];
                bfr[nt][1] = bp[4 * SB];
            }
#pragma unroll
            for (int mt = 0; mt < 4; mt++)
#pragma unroll
                for (int nt = 0; nt < 4; nt++)
                    mma_tf32(acc[mt][nt][0], acc[mt][nt][1],
                             acc[mt][nt][2], acc[mt][nt][3],
                             afr[mt][0], afr[mt][1], afr[mt][2], afr[mt][3],
                             bfr[nt][0], bfr[nt][1]);
        }

        if (it + 1 < nk) {
            int nb = buf ^ 1;
            uint32_t* ad = &As[nb][ar * SA + ac];
            *(uint4*)(ad)     = cvt4(a0v);
            *(uint4*)(ad + 4) = cvt4(a1v);
            uint32_t* bd = &Bs[nb][br * SB + bc];
            *(uint4*)(bd)          = cvt4(b0v);
            *(uint4*)(bd + 8 * SB) = cvt4(b1v);
            __syncthreads();
            buf = nb;
        }
    }

    // epilogue
#pragma unroll
    for (int mt = 0; mt < 4; mt++) {
        int row0 = bm + wm + mt * 16 + gid;
#pragma unroll
        for (int nt = 0; nt < 4; nt++) {
            int col = bn + wn + nt * 8 + 2 * tig;
            float bx = bias[col], by = bias[col + 1];
            float2 v0, v1;
            v0.x = acc[mt][nt][0] + bx; v0.y = acc[mt][nt][1] + by;
            v1.x = acc[mt][nt][2] + bx; v1.y = acc[mt][nt][3] + by;
            if (RELU) {
                v0.x = fmaxf(v0.x, 0.f); v0.y = fmaxf(v0.y, 0.f);
                v1.x = fmaxf(v1.x, 0.f); v1.y = fmaxf(v1.y, 0.f);
            }
            *(float2*)&C[(size_t)row0 * N + col]       = v0;
            *(float2*)&C[(size_t)(row0 + 8) * N + col] = v1;
        }
    }
}

// ---------------------------------------------------------------------------
// Flash attention (fp32, online softmax) — unchanged from R1.
// ---------------------------------------------------------------------------
#define ATTN_SMEM (17408 + 17408 + 16384 + 17408)   // Qs + Ks + Vs + Ps = 68608 B

__global__ void __launch_bounds__(256, 2) attn_kernel(
    const float* __restrict__ Qg, const float* __restrict__ Kg,
    const float* __restrict__ Vg, float* __restrict__ Og)
{
    extern __shared__ float smem[];
    float4* Qs = (float4*)smem;            // [64][17]
    float4* Ks = Qs + 64 * 17;             // [64][17]
    float4* Vs = Ks + 64 * 17;             // [64][16]
    float*  Ps = (float*)(Vs + 64 * 16);   // [64][68]

    int tid = threadIdx.x;
    int qt = blockIdx.x, h = blockIdx.y, b = blockIdx.z;
    int r = tid >> 2, c4 = tid & 3;

    const float* qbase = Qg + (size_t)(b * SEQ + qt * 64) * DM + h * DHD;
#pragma unroll
    for (int i = 0; i < 4; i++) {
        int id = tid + i * 256;
        int row = id >> 4, col = id & 15;
        Qs[row * 17 + col] = *(const float4*)(qbase + (size_t)row * DM + col * 4);
    }

    float m_prev = -1e30f, l = 0.f;
    float4 Oa[4];
#pragma unroll
    for (int i = 0; i < 4; i++) Oa[i] = make_float4(0.f, 0.f, 0.f, 0.f);

    for (int kt = 0; kt < 16; kt++) {
        const float* kbase = Kg + (size_t)(b * SEQ + kt * 64) * DM + h * DHD;
        const float* vbase = Vg + (size_t)(b * SEQ + kt * 64) * DM + h * DHD;
        __syncthreads();
#pragma unroll
        for (int i = 0; i < 4; i++) {
            int id = tid + i * 256;
            int row = id >> 4, col = id & 15;
            Ks[row * 17 + col] = *(const float4*)(kbase + (size_t)row * DM + col * 4);
            Vs[row * 16 + col] = *(const float4*)(vbase + (size_t)row * DM + col * 4);
        }
        __syncthreads();

        float s[16];
#pragma unroll
        for (int j = 0; j < 16; j++) s[j] = 0.f;
#pragma unroll
        for (int e = 0; e < 16; e++) {
            float4 q = Qs[r * 17 + e];
#pragma unroll
            for (int j = 0; j < 16; j++) {
                float4 k4 = Ks[(j * 4 + c4) * 17 + e];
                s[j] += q.x * k4.x + q.y * k4.y + q.z * k4.z + q.w * k4.w;
            }
        }
        float mt = -1e30f;
#pragma unroll
        for (int j = 0; j < 16; j++) { s[j] *= 0.125f; mt = fmaxf(mt, s[j]); }
        mt = fmaxf(mt, __shfl_xor_sync(0xffffffffu, mt, 1));
        mt = fmaxf(mt, __shfl_xor_sync(0xffffffffu, mt, 2));
        float m_new = fmaxf(m_prev, mt);

        float p[16], lloc = 0.f;
#pragma unroll
        for (int j = 0; j < 16; j++) { p[j] = __expf(s[j] - m_new); lloc += p[j]; }
        lloc += __shfl_xor_sync(0xffffffffu, lloc, 1);
        lloc += __shfl_xor_sync(0xffffffffu, lloc, 2);
        float alpha = __expf(m_prev - m_new);
        l = l * alpha + lloc;
#pragma unroll
        for (int i = 0; i < 4; i++) {
            Oa[i].x *= alpha; Oa[i].y *= alpha; Oa[i].z *= alpha; Oa[i].w *= alpha;
        }

#pragma unroll
        for (int j = 0; j < 16; j++) Ps[r * 68 + j * 4 + c4] = p[j];
        __syncthreads();

#pragma unroll
        for (int k = 0; k < 64; k++) {
            float pv = Ps[r * 68 + k];
#pragma unroll
            for (int i = 0; i < 4; i++) {
                float4 v = Vs[k * 16 + c4 * 4 + i];
                Oa[i].x += pv * v.x; Oa[i].y += pv * v.y;
                Oa[i].z += pv * v.z; Oa[i].w += pv * v.w;
            }
        }
        m_prev = m_new;
    }

    float inv = 1.f / l;
    float4* obase = (float4*)(Og + (size_t)(b * SEQ + qt * 64 + r) * DM + h * DHD);
#pragma unroll
    for (int i = 0; i < 4; i++) {
        float4 v = Oa[i];
        v.x *= inv; v.y *= inv; v.z *= inv; v.w *= inv;
        obase[c4 * 4 + i] = v;
    }
}

// ---------------------------------------------------------------------------
// Fused residual + LayerNorm — unchanged from R1.
// ---------------------------------------------------------------------------
__global__ void __launch_bounds__(256) ln_kernel(
    const float* __restrict__ Xa, const float* __restrict__ Xb,
    const float* __restrict__ g, const float* __restrict__ beta,
    float* __restrict__ out)
{
    int row = blockIdx.x;
    const float* a = Xa + (size_t)row * DM;
    const float* b = Xb + (size_t)row * DM;
    float vloc[4];
    float s = 0.f, ss = 0.f;
#pragma unroll
    for (int k = 0; k < 4; k++) {
        int i = threadIdx.x + k * 256;
        float v = a[i] + b[i];
        vloc[k] = v; s += v; ss += v * v;
    }
#pragma unroll
    for (int o = 16; o > 0; o >>= 1) {
        s  += __shfl_xor_sync(0xffffffffu, s, o);
        ss += __shfl_xor_sync(0xffffffffu, ss, o);
    }
    __shared__ float red[16];
    __shared__ float mu_s, rstd_s;
    int wid = threadIdx.x >> 5, lid = threadIdx.x & 31;
    if (lid == 0) { red[wid] = s; red[8 + wid] = ss; }
    __syncthreads();
    if (threadIdx.x == 0) {
        float S = 0.f, SS = 0.f;
        for (int i = 0; i < 8; i++) { S += red[i]; SS += red[8 + i]; }
        float mu = S * (1.f / DM);
        float var = SS * (1.f / DM) - mu * mu;
        mu_s = mu;
        rstd_s = rsqrtf(var + 1e-5f);
    }
    __syncthreads();
    float mu = mu_s, rstd = rstd_s;
    float* o = out + (size_t)row * DM;
#pragma unroll
    for (int k = 0; k < 4; k++) {
        int i = threadIdx.x + k * 256;
        o[i] = (vloc[k] - mu) * rstd * g[i] + beta[i];
    }
}

// ---------------------------------------------------------------------------
// Launch
// ---------------------------------------------------------------------------
extern "C" void kernel_launch(void* const* d_in, const int* in_sizes, int n_in,
                              void* d_out, int out_size)
{
    const float* q_in = (const float*)d_in[0];
    const float* mA   = (const float*)d_in[1];
    const float* mB   = (const float*)d_in[2];
    const float* Wq1 = (const float*)d_in[3];  const float* bq1 = (const float*)d_in[4];
    const float* Wk1 = (const float*)d_in[5];  const float* bk1 = (const float*)d_in[6];
    const float* Wv1 = (const float*)d_in[7];  const float* bv1 = (const float*)d_in[8];
    const float* Wo1 = (const float*)d_in[9];  const float* bo1 = (const float*)d_in[10];
    const float* Wq2 = (const float*)d_in[11]; const float* bq2 = (const float*)d_in[12];
    const float* Wk2 = (const float*)d_in[13]; const float* bk2 = (const float*)d_in[14];
    const float* Wv2 = (const float*)d_in[15]; const float* bv2 = (const float*)d_in[16];
    const float* Wo2 = (const float*)d_in[17]; const float* bo2 = (const float*)d_in[18];
    const float* W1  = (const float*)d_in[19]; const float* b1  = (const float*)d_in[20];
    const float* W2  = (const float*)d_in[21]; const float* b2  = (const float*)d_in[22];
    const float* g1  = (const float*)d_in[23]; const float* be1 = (const float*)d_in[24];
    const float* g2  = (const float*)d_in[25]; const float* be2 = (const float*)d_in[26];
    const float* g3  = (const float*)d_in[27]; const float* be3 = (const float*)d_in[28];
    float* out = (float*)d_out;

    float *pWp, *pQ, *pK, *pV, *pAttn, *pTmp, *pX1, *pX2, *pHid;
    cudaGetSymbolAddress((void**)&pWp,   g_Wp);
    cudaGetSymbolAddress((void**)&pQ,    g_Q);
    cudaGetSymbolAddress((void**)&pK,    g_K);
    cudaGetSymbolAddress((void**)&pV,    g_V);
    cudaGetSymbolAddress((void**)&pAttn, g_Attn);
    cudaGetSymbolAddress((void**)&pTmp,  g_Tmp);
    cudaGetSymbolAddress((void**)&pX1,   g_X1);
    cudaGetSymbolAddress((void**)&pX2,   g_X2);
    cudaGetSymbolAddress((void**)&pHid,  g_Hid);
    float* pW0  = pWp;
    float* pW1p = pWp + DM * DM;
    float* pW2p = pWp + 2 * DM * DM;

    cudaFuncSetAttribute(attn_kernel, cudaFuncAttributeMaxDynamicSharedMemorySize, ATTN_SMEM);

    const dim3 blk(256);
    const dim3 gPack(DM * DM / 256);
    const dim3 gGemm1k(DM / 128, NTOK / 128);        // N=1024
    const dim3 gGemmFF1(HIDN / 128, NTOK / 128);     // N=4096
    const dim3 gAttn(SEQ / 64, NH, BATCH);
    const dim3 gLN(NTOK);

    // ---- Attention block 1: Q from query, K/V from modality_A ----
    pack_w_kernel<<<gPack, blk>>>(Wq1, pW0);
    pack_w_kernel<<<gPack, blk>>>(Wk1, pW1p);
    pack_w_kernel<<<gPack, blk>>>(Wv1, pW2p);
    tc_gemm_kernel<false><<<gGemm1k, blk>>>(q_in, pW0,  bq1, pQ, NTOK, DM, DM);
    tc_gemm_kernel<false><<<gGemm1k, blk>>>(mA,   pW1p, bk1, pK, NTOK, DM, DM);
    tc_gemm_kernel<false><<<gGemm1k, blk>>>(mA,   pW2p, bv1, pV, NTOK, DM, DM);
    attn_kernel<<<gAttn, blk, ATTN_SMEM>>>(pQ, pK, pV, pAttn);
    tc_gemm_kernel<false><<<gGemm1k, blk>>>(pAttn, Wo1, bo1, pTmp, NTOK, DM, DM);
    ln_kernel<<<gLN, blk>>>(q_in, pTmp, g1, be1, pX1);

    // ---- Attention block 2: Q from x1, K/V from modality_B ----
    pack_w_kernel<<<gPack, blk>>>(Wq2, pW0);
    pack_w_kernel<<<gPack, blk>>>(Wk2, pW1p);
    pack_w_kernel<<<gPack, blk>>>(Wv2, pW2p);
    tc_gemm_kernel<false><<<gGemm1k, blk>>>(pX1, pW0,  bq2, pQ, NTOK, DM, DM);
    tc_gemm_kernel<false><<<gGemm1k, blk>>>(mB,  pW1p, bk2, pK, NTOK, DM, DM);
    tc_gemm_kernel<false><<<gGemm1k, blk>>>(mB,  pW2p, bv2, pV, NTOK, DM, DM);
    attn_kernel<<<gAttn, blk, ATTN_SMEM>>>(pQ, pK, pV, pAttn);
    tc_gemm_kernel<false><<<gGemm1k, blk>>>(pAttn, Wo2, bo2, pTmp, NTOK, DM, DM);
    ln_kernel<<<gLN, blk>>>(pX1, pTmp, g2, be2, pX2);

    // ---- FFN ----
    tc_gemm_kernel<true><<<gGemmFF1, blk>>>(pX2, W1, b1, pHid, NTOK, HIDN, DM);
    tc_gemm_kernel<false><<<gGemm1k, blk>>>(pHid, W2, b2, pTmp, NTOK, DM, HIDN);
    ln_kernel<<<gLN, blk>>>(pX2, pTmp, g3, be3, out);
}

// round 4
// speedup vs baseline: 3.4930x; 2.4013x over previous
#include <cuda_runtime.h>
#include <math.h>
#include <stdint.h>

// Problem constants
#define DM   1024          // model dim
#define SEQ  1024
#define BATCH 4
#define NTOK (BATCH*SEQ)   // 4096 tokens
#define HIDN 4096
#define NH   16
#define DHD  64

// ---------------------------------------------------------------------------
// Scratch (device globals; no allocation anywhere)
// ---------------------------------------------------------------------------
__device__ float g_Wp[3][DM*DM];        // packed Q/K/V weights  (12 MB)
__device__ float g_Q[NTOK*DM];
__device__ float g_K[NTOK*DM];
__device__ float g_V[NTOK*DM];
__device__ float g_Attn[NTOK*DM];
__device__ float g_Tmp[NTOK*DM];
__device__ float g_X1[NTOK*DM];
__device__ float g_X2[NTOK*DM];
__device__ float g_Hid[NTOK*HIDN];      // 64 MB

// ---------------------------------------------------------------------------
// tf32 helpers
// ---------------------------------------------------------------------------
__device__ __forceinline__ uint32_t to_tf32(float x) {
    uint32_t y;
    asm("cvt.rna.tf32.f32 %0, %1;" : "=r"(y) : "f"(x));
    return y;
}

__device__ __forceinline__ void mma_tf32(
    float& d0, float& d1, float& d2, float& d3,
    uint32_t a0, uint32_t a1, uint32_t a2, uint32_t a3,
    uint32_t b0, uint32_t b1)
{
    asm volatile(
        "mma.sync.aligned.m16n8k8.row.col.f32.tf32.tf32.f32 "
        "{%0,%1,%2,%3}, {%4,%5,%6,%7}, {%8,%9}, {%0,%1,%2,%3};"
        : "+f"(d0), "+f"(d1), "+f"(d2), "+f"(d3)
        : "r"(a0), "r"(a1), "r"(a2), "r"(a3), "r"(b0), "r"(b1));
}

__device__ __forceinline__ uint4 cvt4(float4 v) {
    uint4 u;
    u.x = to_tf32(v.x); u.y = to_tf32(v.y);
    u.z = to_tf32(v.z); u.w = to_tf32(v.w);
    return u;
}

// ---------------------------------------------------------------------------
// Pack per-head weight [H, D, DH] -> standard row-major [D, H*DH]
// ---------------------------------------------------------------------------
__global__ void pack_w_kernel(const float* __restrict__ W, float* __restrict__ Wp) {
    int idx = blockIdx.x * 256 + threadIdx.x;      // over DM*DM
    int n = idx & (DM - 1);
    int d = idx >> 10;
    int h = n >> 6, e = n & 63;
    Wp[idx] = W[h * (DM * DHD) + d * DHD + e];
}

// ---------------------------------------------------------------------------
// TF32 tensor-core GEMM (unchanged from R3)
// ---------------------------------------------------------------------------
#define BM 128
#define BN 128
#define BK 16
#define SA 20
#define SB 136

template<bool RELU>
__global__ void __launch_bounds__(256) tc_gemm_kernel(
    const float* __restrict__ A, const float* __restrict__ B,
    const float* __restrict__ bias, float* __restrict__ C,
    int M, int N, int K)
{
    __shared__ uint32_t As[2][BM * SA];
    __shared__ uint32_t Bs[2][BK * SB];

    int tid  = threadIdx.x;
    int wid  = tid >> 5, lane = tid & 31;
    int gid  = lane >> 2;
    int tig  = lane & 3;
    int wm   = (wid >> 2) * 64;
    int wn   = (wid & 3) * 32;

    int bm = blockIdx.y * BM;
    int bn = blockIdx.x * BN;

    int ar = tid >> 1;
    int ac = (tid & 1) * 8;
    int br = tid >> 5;
    int bc = (tid & 31) * 4;

    const float* Aptr = A + (size_t)(bm + ar) * K + ac;
    const float* Bptr = B + (size_t)br * N + bn + bc;

    float4 a0v = *(const float4*)(Aptr);
    float4 a1v = *(const float4*)(Aptr + 4);
    float4 b0v = *(const float4*)(Bptr);
    float4 b1v = *(const float4*)(Bptr + (size_t)8 * N);

    float acc[4][4][4];
#pragma unroll
    for (int i = 0; i < 4; i++)
#pragma unroll
        for (int j = 0; j < 4; j++)
#pragma unroll
            for (int c = 0; c < 4; c++) acc[i][j][c] = 0.f;

    {
        uint32_t* ad = &As[0][ar * SA + ac];
        *(uint4*)(ad)     = cvt4(a0v);
        *(uint4*)(ad + 4) = cvt4(a1v);
        uint32_t* bd = &Bs[0][br * SB + bc];
        *(uint4*)(bd)          = cvt4(b0v);
        *(uint4*)(bd + 8 * SB) = cvt4(b1v);
    }
    __syncthreads();

    int nk = K / BK;
    int buf = 0;

    for (int it = 0; it < nk; ++it) {
        if (it + 1 < nk) {
            const float* An = Aptr + (it + 1) * BK;
            const float* Bn = Bptr + (size_t)(it + 1) * BK * N;
            a0v = *(const float4*)(An);
            a1v = *(const float4*)(An + 4);
            b0v = *(const float4*)(Bn);
            b1v = *(const float4*)(Bn + (size_t)8 * N);
        }

#pragma unroll
        for (int ks = 0; ks < 2; ks++) {
            int k0 = ks * 8;
            uint32_t afr[4][4];
            uint32_t bfr[4][2];
#pragma unroll
            for (int mt = 0; mt < 4; mt++) {
                const uint32_t* ap = &As[buf][(wm + mt * 16 + gid) * SA + k0 + tig];
                afr[mt][0] = ap[0];
                afr[mt][1] = ap[8 * SA];
                afr[mt][2] = ap[4];
                afr[mt][3] = ap[8 * SA + 4];
            }
#pragma unroll
            for (int nt = 0; nt < 4; nt++) {
                const uint32_t* bp = &Bs[buf][(k0 + tig) * SB + wn + nt * 8 + gid];
                bfr[nt][0] = bp[0];
                bfr[nt][1] = bp[4 * SB];
            }
#pragma unroll
            for (int mt = 0; mt < 4; mt++)
#pragma unroll
                for (int nt = 0; nt < 4; nt++)
                    mma_tf32(acc[mt][nt][0], acc[mt][nt][1],
                             acc[mt][nt][2], acc[mt][nt][3],
                             afr[mt][0], afr[mt][1], afr[mt][2], afr[mt][3],
                             bfr[nt][0], bfr[nt][1]);
        }

        if (it + 1 < nk) {
            int nb = buf ^ 1;
            uint32_t* ad = &As[nb][ar * SA + ac];
            *(uint4*)(ad)     = cvt4(a0v);
            *(uint4*)(ad + 4) = cvt4(a1v);
            uint32_t* bd = &Bs[nb][br * SB + bc];
            *(uint4*)(bd)          = cvt4(b0v);
            *(uint4*)(bd + 8 * SB) = cvt4(b1v);
            __syncthreads();
            buf = nb;
        }
    }

#pragma unroll
    for (int mt = 0; mt < 4; mt++) {
        int row0 = bm + wm + mt * 16 + gid;
#pragma unroll
        for (int nt = 0; nt < 4; nt++) {
            int col = bn + wn + nt * 8 + 2 * tig;
            float bx = bias[col], by = bias[col + 1];
            float2 v0, v1;
            v0.x = acc[mt][nt][0] + bx; v0.y = acc[mt][nt][1] + by;
            v1.x = acc[mt][nt][2] + bx; v1.y = acc[mt][nt][3] + by;
            if (RELU) {
                v0.x = fmaxf(v0.x, 0.f); v0.y = fmaxf(v0.y, 0.f);
                v1.x = fmaxf(v1.x, 0.f); v1.y = fmaxf(v1.y, 0.f);
            }
            *(float2*)&C[(size_t)row0 * N + col]       = v0;
            *(float2*)&C[(size_t)(row0 + 8) * N + col] = v1;
        }
    }
}

// ---------------------------------------------------------------------------
// Tensor-core flash attention (tf32 mma for QK^T and PV).
// Block: 64 q-rows x 1 head. 128 threads = 4 warps; warp w owns rows
// [w*16, w*16+16). Online softmax state per thread covers rows gid and gid+8.
// Smem strides: Ks 68 (banks 4*gid+tig), Vs 72 (banks 8*tig+gid), Ps 68.
// ---------------------------------------------------------------------------
#define AT_SK 68
#define AT_SV 72
#define AT_SP 68
#define ATTN_SMEM ((64*AT_SK + 64*AT_SV + 64*AT_SP) * 4)   // 53248 bytes

__global__ void __launch_bounds__(128, 3) attn_tc_kernel(
    const float* __restrict__ Qg, const float* __restrict__ Kg,
    const float* __restrict__ Vg, float* __restrict__ Og)
{
    extern __shared__ uint32_t smu[];
    uint32_t* Ks = smu;                  // [64][68] tf32 bits
    uint32_t* Vs = Ks + 64 * AT_SK;      // [64][72] tf32 bits
    uint32_t* Ps = Vs + 64 * AT_SV;      // [64][68] tf32 bits (warp-private rows)
    float* Qstage = (float*)Ps;          // reused for Q staging at start

    int tid  = threadIdx.x;
    int warp = tid >> 5, lane = tid & 31;
    int gid  = lane >> 2, tig = lane & 3;
    int wm   = warp * 16;
    int qt = blockIdx.x, h = blockIdx.y, b = blockIdx.z;

    // ---- stage Q tile (64x64) into smem, coalesced ----
    const float* qbase = Qg + (size_t)(b * SEQ + qt * 64) * DM + h * DHD;
#pragma unroll
    for (int i = 0; i < 8; i++) {
        int id  = tid + i * 128;
        int row = id >> 4, c = (id & 15) * 4;
        float4 v = *(const float4*)(qbase + (size_t)row * DM + c);
        float* d = Qstage + row * AT_SP + c;
        d[0] = v.x; d[1] = v.y; d[2] = v.z; d[3] = v.w;
    }
    __syncthreads();

    // ---- build Q A-fragments in registers (pre-scaled by 1/8, tf32) ----
    uint32_t qa[8][4];
#pragma unroll
    for (int ks = 0; ks < 8; ks++) {
        qa[ks][0] = to_tf32(Qstage[(wm + gid)     * AT_SP + ks * 8 + tig]     * 0.125f);
        qa[ks][1] = to_tf32(Qstage[(wm + gid + 8) * AT_SP + ks * 8 + tig]     * 0.125f);
        qa[ks][2] = to_tf32(Qstage[(wm + gid)     * AT_SP + ks * 8 + tig + 4] * 0.125f);
        qa[ks][3] = to_tf32(Qstage[(wm + gid + 8) * AT_SP + ks * 8 + tig + 4] * 0.125f);
    }

    float oa[8][4];
#pragma unroll
    for (int nt = 0; nt < 8; nt++) {
        oa[nt][0] = 0.f; oa[nt][1] = 0.f; oa[nt][2] = 0.f; oa[nt][3] = 0.f;
    }
    float m0 = -1e30f, m1 = -1e30f, l0 = 0.f, l1 = 0.f;

    for (int kt = 0; kt < 16; kt++) {
        __syncthreads();   // prior iter reads of Ks/Vs (and Qstage->Ps reuse) done
        const float* kb = Kg + (size_t)(b * SEQ + kt * 64) * DM + h * DHD;
        const float* vb = Vg + (size_t)(b * SEQ + kt * 64) * DM + h * DHD;
#pragma unroll
        for (int i = 0; i < 8; i++) {
            int id  = tid + i * 128;
            int row = id >> 4, c = (id & 15) * 4;
            float4 kv = *(const float4*)(kb + (size_t)row * DM + c);
            float4 vv = *(const float4*)(vb + (size_t)row * DM + c);
            *(uint4*)(Ks + row * AT_SK + c) = cvt4(kv);
            *(uint4*)(Vs + row * AT_SV + c) = cvt4(vv);
        }
        __syncthreads();

        // ---- scores S = (Q/8) @ K^T  (16x64 per warp) ----
        float sc[8][4];
#pragma unroll
        for (int nt = 0; nt < 8; nt++) {
            sc[nt][0] = 0.f; sc[nt][1] = 0.f; sc[nt][2] = 0.f; sc[nt][3] = 0.f;
        }
#pragma unroll
        for (int ks = 0; ks < 8; ks++) {
#pragma unroll
            for (int nt = 0; nt < 8; nt++) {
                uint32_t b0 = Ks[(nt * 8 + gid) * AT_SK + ks * 8 + tig];
                uint32_t b1 = Ks[(nt * 8 + gid) * AT_SK + ks * 8 + tig + 4];
                mma_tf32(sc[nt][0], sc[nt][1], sc[nt][2], sc[nt][3],
                         qa[ks][0], qa[ks][1], qa[ks][2], qa[ks][3], b0, b1);
            }
        }

        // ---- online softmax (rows gid / gid+8; reduce over 4 lanes sharing row) ----
        float mt0 = -1e30f, mt1 = -1e30f;
#pragma unroll
        for (int nt = 0; nt < 8; nt++) {
            mt0 = fmaxf(mt0, fmaxf(sc[nt][0], sc[nt][1]));
            mt1 = fmaxf(mt1, fmaxf(sc[nt][2], sc[nt][3]));
        }
        mt0 = fmaxf(mt0, __shfl_xor_sync(0xffffffffu, mt0, 1));
        mt0 = fmaxf(mt0, __shfl_xor_sync(0xffffffffu, mt0, 2));
        mt1 = fmaxf(mt1, __shfl_xor_sync(0xffffffffu, mt1, 1));
        mt1 = fmaxf(mt1, __shfl_xor_sync(0xffffffffu, mt1, 2));
        float mn0 = fmaxf(m0, mt0), mn1 = fmaxf(m1, mt1);
        float a0 = __expf(m0 - mn0), a1 = __expf(m1 - mn1);

        float s0 = 0.f, s1 = 0.f;
#pragma unroll
        for (int nt = 0; nt < 8; nt++) {
            sc[nt][0] = __expf(sc[nt][0] - mn0);
            sc[nt][1] = __expf(sc[nt][1] - mn0);
            sc[nt][2] = __expf(sc[nt][2] - mn1);
            sc[nt][3] = __expf(sc[nt][3] - mn1);
            s0 += sc[nt][0] + sc[nt][1];
            s1 += sc[nt][2] + sc[nt][3];
        }
        s0 += __shfl_xor_sync(0xffffffffu, s0, 1);
        s0 += __shfl_xor_sync(0xffffffffu, s0, 2);
        s1 += __shfl_xor_sync(0xffffffffu, s1, 1);
        s1 += __shfl_xor_sync(0xffffffffu, s1, 2);
        l0 = l0 * a0 + s0;
        l1 = l1 * a1 + s1;
#pragma unroll
        for (int nt = 0; nt < 8; nt++) {
            oa[nt][0] *= a0; oa[nt][1] *= a0;
            oa[nt][2] *= a1; oa[nt][3] *= a1;
        }
        m0 = mn0; m1 = mn1;

        // ---- P: C-layout -> A-layout via warp-private smem slab (tf32) ----
#pragma unroll
        for (int nt = 0; nt < 8; nt++) {
            uint2 p01; p01.x = to_tf32(sc[nt][0]); p01.y = to_tf32(sc[nt][1]);
            *(uint2*)&Ps[(wm + gid) * AT_SP + nt * 8 + 2 * tig] = p01;
            uint2 p23; p23.x = to_tf32(sc[nt][2]); p23.y = to_tf32(sc[nt][3]);
            *(uint2*)&Ps[(wm + gid + 8) * AT_SP + nt * 8 + 2 * tig] = p23;
        }
        __syncwarp();

        // ---- O += P @ V ----
#pragma unroll
        for (int ks = 0; ks < 8; ks++) {
            uint32_t pa0 = Ps[(wm + gid)     * AT_SP + ks * 8 + tig];
            uint32_t pa1 = Ps[(wm + gid + 8) * AT_SP + ks * 8 + tig];
            uint32_t pa2 = Ps[(wm + gid)     * AT_SP + ks * 8 + tig + 4];
            uint32_t pa3 = Ps[(wm + gid + 8) * AT_SP + ks * 8 + tig + 4];
#pragma unroll
            for (int nt = 0; nt < 8; nt++) {
                uint32_t b0 = Vs[(ks * 8 + tig)     * AT_SV + nt * 8 + gid];
                uint32_t b1 = Vs[(ks * 8 + tig + 4) * AT_SV + nt * 8 + gid];
                mma_tf32(oa[nt][0], oa[nt][1], oa[nt][2], oa[nt][3],
                         pa0, pa1, pa2, pa3, b0, b1);
            }
        }
    }

    float i0 = 1.f / l0, i1 = 1.f / l1;
    float* ob = Og + (size_t)(b * SEQ + qt * 64) * DM + h * DHD;
#pragma unroll
    for (int nt = 0; nt < 8; nt++) {
        float2 v0; v0.x = oa[nt][0] * i0; v0.y = oa[nt][1] * i0;
        *(float2*)&ob[(size_t)(wm + gid) * DM + nt * 8 + 2 * tig] = v0;
        float2 v1; v1.x = oa[nt][2] * i1; v1.y = oa[nt][3] * i1;
        *(float2*)&ob[(size_t)(wm + gid + 8) * DM + nt * 8 + 2 * tig] = v1;
    }
}

// ---------------------------------------------------------------------------
// Fused residual + LayerNorm — unchanged.
// ---------------------------------------------------------------------------
__global__ void __launch_bounds__(256) ln_kernel(
    const float* __restrict__ Xa, const float* __restrict__ Xb,
    const float* __restrict__ g, const float* __restrict__ beta,
    float* __restrict__ out)
{
    int row = blockIdx.x;
    const float* a = Xa + (size_t)row * DM;
    const float* b = Xb + (size_t)row * DM;
    float vloc[4];
    float s = 0.f, ss = 0.f;
#pragma unroll
    for (int k = 0; k < 4; k++) {
        int i = threadIdx.x + k * 256;
        float v = a[i] + b[i];
        vloc[k] = v; s += v; ss += v * v;
    }
#pragma unroll
    for (int o = 16; o > 0; o >>= 1) {
        s  += __shfl_xor_sync(0xffffffffu, s, o);
        ss += __shfl_xor_sync(0xffffffffu, ss, o);
    }
    __shared__ float red[16];
    __shared__ float mu_s, rstd_s;
    int wid = threadIdx.x >> 5, lid = threadIdx.x & 31;
    if (lid == 0) { red[wid] = s; red[8 + wid] = ss; }
    __syncthreads();
    if (threadIdx.x == 0) {
        float S = 0.f, SS = 0.f;
        for (int i = 0; i < 8; i++) { S += red[i]; SS += red[8 + i]; }
        float mu = S * (1.f / DM);
        float var = SS * (1.f / DM) - mu * mu;
        mu_s = mu;
        rstd_s = rsqrtf(var + 1e-5f);
    }
    __syncthreads();
    float mu = mu_s, rstd = rstd_s;
    float* o = out + (size_t)row * DM;
#pragma unroll
    for (int k = 0; k < 4; k++) {
        int i = threadIdx.x + k * 256;
        o[i] = (vloc[k] - mu) * rstd * g[i] + beta[i];
    }
}

// ---------------------------------------------------------------------------
// Launch
// ---------------------------------------------------------------------------
extern "C" void kernel_launch(void* const* d_in, const int* in_sizes, int n_in,
                              void* d_out, int out_size)
{
    const float* q_in = (const float*)d_in[0];
    const float* mA   = (const float*)d_in[1];
    const float* mB   = (const float*)d_in[2];
    const float* Wq1 = (const float*)d_in[3];  const float* bq1 = (const float*)d_in[4];
    const float* Wk1 = (const float*)d_in[5];  const float* bk1 = (const float*)d_in[6];
    const float* Wv1 = (const float*)d_in[7];  const float* bv1 = (const float*)d_in[8];
    const float* Wo1 = (const float*)d_in[9];  const float* bo1 = (const float*)d_in[10];
    const float* Wq2 = (const float*)d_in[11]; const float* bq2 = (const float*)d_in[12];
    const float* Wk2 = (const float*)d_in[13]; const float* bk2 = (const float*)d_in[14];
    const float* Wv2 = (const float*)d_in[15]; const float* bv2 = (const float*)d_in[16];
    const float* Wo2 = (const float*)d_in[17]; const float* bo2 = (const float*)d_in[18];
    const float* W1  = (const float*)d_in[19]; const float* b1  = (const float*)d_in[20];
    const float* W2  = (const float*)d_in[21]; const float* b2  = (const float*)d_in[22];
    const float* g1  = (const float*)d_in[23]; const float* be1 = (const float*)d_in[24];
    const float* g2  = (const float*)d_in[25]; const float* be2 = (const float*)d_in[26];
    const float* g3  = (const float*)d_in[27]; const float* be3 = (const float*)d_in[28];
    float* out = (float*)d_out;

    float *pWp, *pQ, *pK, *pV, *pAttn, *pTmp, *pX1, *pX2, *pHid;
    cudaGetSymbolAddress((void**)&pWp,   g_Wp);
    cudaGetSymbolAddress((void**)&pQ,    g_Q);
    cudaGetSymbolAddress((void**)&pK,    g_K);
    cudaGetSymbolAddress((void**)&pV,    g_V);
    cudaGetSymbolAddress((void**)&pAttn, g_Attn);
    cudaGetSymbolAddress((void**)&pTmp,  g_Tmp);
    cudaGetSymbolAddress((void**)&pX1,   g_X1);
    cudaGetSymbolAddress((void**)&pX2,   g_X2);
    cudaGetSymbolAddress((void**)&pHid,  g_Hid);
    float* pW0  = pWp;
    float* pW1p = pWp + DM * DM;
    float* pW2p = pWp + 2 * DM * DM;

    cudaFuncSetAttribute(attn_tc_kernel, cudaFuncAttributeMaxDynamicSharedMemorySize, ATTN_SMEM);

    const dim3 blk(256);
    const dim3 ablk(128);
    const dim3 gPack(DM * DM / 256);
    const dim3 gGemm1k(DM / 128, NTOK / 128);        // N=1024
    const dim3 gGemmFF1(HIDN / 128, NTOK / 128);     // N=4096
    const dim3 gAttn(SEQ / 64, NH, BATCH);
    const dim3 gLN(NTOK);

    // ---- Attention block 1: Q from query, K/V from modality_A ----
    pack_w_kernel<<<gPack, blk>>>(Wq1, pW0);
    pack_w_kernel<<<gPack, blk>>>(Wk1, pW1p);
    pack_w_kernel<<<gPack, blk>>>(Wv1, pW2p);
    tc_gemm_kernel<false><<<gGemm1k, blk>>>(q_in, pW0,  bq1, pQ, NTOK, DM, DM);
    tc_gemm_kernel<false><<<gGemm1k, blk>>>(mA,   pW1p, bk1, pK, NTOK, DM, DM);
    tc_gemm_kernel<false><<<gGemm1k, blk>>>(mA,   pW2p, bv1, pV, NTOK, DM, DM);
    attn_tc_kernel<<<gAttn, ablk, ATTN_SMEM>>>(pQ, pK, pV, pAttn);
    tc_gemm_kernel<false><<<gGemm1k, blk>>>(pAttn, Wo1, bo1, pTmp, NTOK, DM, DM);
    ln_kernel<<<gLN, blk>>>(q_in, pTmp, g1, be1, pX1);

    // ---- Attention block 2: Q from x1, K/V from modality_B ----
    pack_w_kernel<<<gPack, blk>>>(Wq2, pW0);
    pack_w_kernel<<<gPack, blk>>>(Wk2, pW1p);
    pack_w_kernel<<<gPack, blk>>>(Wv2, pW2p);
    tc_gemm_kernel<false><<<gGemm1k, blk>>>(pX1, pW0,  bq2, pQ, NTOK, DM, DM);
    tc_gemm_kernel<false><<<gGemm1k, blk>>>(mB,  pW1p, bk2, pK, NTOK, DM, DM);
    tc_gemm_kernel<false><<<gGemm1k, blk>>>(mB,  pW2p, bv2, pV, NTOK, DM, DM);
    attn_tc_kernel<<<gAttn, ablk, ATTN_SMEM>>>(pQ, pK, pV, pAttn);
    tc_gemm_kernel<false><<<gGemm1k, blk>>>(pAttn, Wo2, bo2, pTmp, NTOK, DM, DM);
    ln_kernel<<<gLN, blk>>>(pX1, pTmp, g2, be2, pX2);

    // ---- FFN ----
    tc_gemm_kernel<true><<<gGemmFF1, blk>>>(pX2, W1, b1, pHid, NTOK, HIDN, DM);
    tc_gemm_kernel<false><<<gGemm1k, blk>>>(pHid, W2, b2, pTmp, NTOK, DM, HIDN);
    ln_kernel<<<gLN, blk>>>(pX2, pTmp, g3, be3, out);
}

// round 6
// speedup vs baseline: 4.1622x; 1.1916x over previous
#include <cuda_runtime.h>
#include <math.h>
#include <stdint.h>

// Problem constants
#define DM   1024          // model dim
#define SEQ  1024
#define BATCH 4
#define NTOK (BATCH*SEQ)   // 4096 tokens
#define HIDN 4096
#define NH   16
#define DHD  64

// ---------------------------------------------------------------------------
// Scratch (device globals; no allocation anywhere)
// ---------------------------------------------------------------------------
__device__ float g_Q[NTOK*DM];
__device__ float g_K[NTOK*DM];
__device__ float g_V[NTOK*DM];
__device__ float g_Attn[NTOK*DM];
__device__ float g_Tmp[NTOK*DM];
__device__ float g_X1[NTOK*DM];
__device__ float g_X2[NTOK*DM];
__device__ float g_Hid[NTOK*HIDN];      // 64 MB

// ---------------------------------------------------------------------------
// tf32 helpers
// ---------------------------------------------------------------------------
__device__ __forceinline__ uint32_t to_tf32(float x) {
    uint32_t y;
    asm("cvt.rna.tf32.f32 %0, %1;" : "=r"(y) : "f"(x));
    return y;
}

__device__ __forceinline__ void mma_tf32(
    float& d0, float& d1, float& d2, float& d3,
    uint32_t a0, uint32_t a1, uint32_t a2, uint32_t a3,
    uint32_t b0, uint32_t b1)
{
    asm volatile(
        "mma.sync.aligned.m16n8k8.row.col.f32.tf32.tf32.f32 "
        "{%0,%1,%2,%3}, {%4,%5,%6,%7}, {%8,%9}, {%0,%1,%2,%3};"
        : "+f"(d0), "+f"(d1), "+f"(d2), "+f"(d3)
        : "r"(a0), "r"(a1), "r"(a2), "r"(a3), "r"(b0), "r"(b1));
}

__device__ __forceinline__ uint4 cvt4(float4 v) {
    uint4 u;
    u.x = to_tf32(v.x); u.y = to_tf32(v.y);
    u.z = to_tf32(v.z); u.w = to_tf32(v.w);
    return u;
}

__device__ __forceinline__ void cp16(uint32_t smem_dst, const void* gsrc) {
    asm volatile("cp.async.ca.shared.global [%0], [%1], 16;\n"
                 :: "r"(smem_dst), "l"(gsrc));
}
__device__ __forceinline__ void cp_commit() {
    asm volatile("cp.async.commit_group;\n" ::: "memory");
}
template<int N>
__device__ __forceinline__ void cp_wait() {
    asm volatile("cp.async.wait_group %0;\n" :: "n"(N) : "memory");
}

// ---------------------------------------------------------------------------
// TF32 tensor-core GEMM: C[M,N] = A[M,K] @ B[K,N] + bias[N]
// Block tile 128x256, BK=16, 256 threads (8 warps 2x4), warp tile 64x64.
// cp.async double buffer; implicit f32->tf32 truncation in mma.
// PERM: B is the original per-head weight [H=16, K=1024, 64]; logical col
//       n maps to  W + (n>>6)*65536 + k*64 + (n&63).
// ---------------------------------------------------------------------------
#define BM 128
#define BN 256
#define BK 16
#define SA 20                 // As row stride (uint32)
#define SBN 264               // Bs row stride (uint32)
#define GEMM_SMEM ((2*BM*SA + 2*BK*SBN) * 4)   // 54272 bytes

template<bool RELU, bool PERM>
__global__ void __launch_bounds__(256) tc_gemm_kernel(
    const float* __restrict__ A, const float* __restrict__ B,
    const float* __restrict__ bias, float* __restrict__ C,
    int M, int N, int K)
{
    extern __shared__ uint32_t sm[];
    uint32_t* As = sm;                 // [2][BM*SA]
    uint32_t* Bs = sm + 2 * BM * SA;   // [2][BK*SBN]

    int tid  = threadIdx.x;
    int wid  = tid >> 5, lane = tid & 31;
    int gid  = lane >> 2;              // 0..7
    int tig  = lane & 3;               // 0..3
    int wm   = (wid >> 2) * 64;        // 0 or 64
    int wn   = (wid & 3) * 64;         // 0..192

    int bm = blockIdx.y * BM;
    int bn = blockIdx.x * BN;

    // loader assignments
    int ar = tid >> 1;                 // A row 0..127
    int ak = (tid & 1) * 8;            // A col base {0,8}
    int br = tid >> 4;                 // B k-row 0..15
    int bt = tid & 15;                 // B col-thread 0..15 (cols 4*bt + 64*j)

    const float* Asrc = A + (size_t)(bm + ar) * K + ak;

    // B source pointers per chunk j (col = 4*bt + 64*j)
    const float* Bsrc[4];
#pragma unroll
    for (int j = 0; j < 4; j++) {
        int n0 = bn + bt * 4 + j * 64;
        if (PERM) Bsrc[j] = B + ((size_t)(n0 >> 6) << 16) + (size_t)br * 64 + (n0 & 63);
        else      Bsrc[j] = B + (size_t)br * N + n0;
    }
    // per-k-tile advance for B sources
    const size_t bstep = PERM ? (size_t)BK * 64 : (size_t)BK * N;

    uint32_t a_sm = (uint32_t)__cvta_generic_to_shared(As);
    uint32_t b_sm = (uint32_t)__cvta_generic_to_shared(Bs);
    uint32_t a_dst0 = a_sm + (ar * SA + ak) * 4;
    uint32_t b_dst0 = b_sm + (br * SBN + bt * 4) * 4;   // element 4*bt (+64*j below)

    float acc[4][8][4];
#pragma unroll
    for (int i = 0; i < 4; i++)
#pragma unroll
        for (int j = 0; j < 8; j++)
#pragma unroll
            for (int c = 0; c < 4; c++) acc[i][j][c] = 0.f;

    int nk = K / BK;

    // prologue: tile 0 -> buf 0
    {
        cp16(a_dst0,      Asrc);
        cp16(a_dst0 + 16, Asrc + 4);
#pragma unroll
        for (int j = 0; j < 4; j++)
            cp16(b_dst0 + j * 64 * 4, Bsrc[j]);
        cp_commit();
    }

    int buf = 0;
    for (int it = 0; it < nk; ++it) {
        cp_wait<0>();
        __syncthreads();

        // prefetch next tile into other buffer
        if (it + 1 < nk) {
            int nb = buf ^ 1;
            const float* An = Asrc + (size_t)(it + 1) * BK;
            uint32_t ad = a_dst0 + nb * (BM * SA * 4);
            cp16(ad,      An);
            cp16(ad + 16, An + 4);
            uint32_t bd = b_dst0 + nb * (BK * SBN * 4);
            size_t off = (size_t)(it + 1) * bstep;
#pragma unroll
            for (int j = 0; j < 4; j++)
                cp16(bd + j * 64 * 4, Bsrc[j] + off);
            cp_commit();
        }

        const uint32_t* Ab = As + buf * (BM * SA);
        const uint32_t* Bb = Bs + buf * (BK * SBN);
#pragma unroll
        for (int ks = 0; ks < 2; ks++) {
            int k0 = ks * 8;
            uint32_t afr[4][4];
            uint32_t bfr[8][2];
#pragma unroll
            for (int mt = 0; mt < 4; mt++) {
                const uint32_t* ap = &Ab[(wm + mt * 16 + gid) * SA + k0 + tig];
                afr[mt][0] = ap[0];
                afr[mt][1] = ap[8 * SA];
                afr[mt][2] = ap[4];
                afr[mt][3] = ap[8 * SA + 4];
            }
#pragma unroll
            for (int nt = 0; nt < 8; nt++) {
                const uint32_t* bp = &Bb[(k0 + tig) * SBN + wn + nt * 8 + gid];
                bfr[nt][0] = bp[0];
                bfr[nt][1] = bp[4 * SBN];
            }
#pragma unroll
            for (int mt = 0; mt < 4; mt++)
#pragma unroll
                for (int nt = 0; nt < 8; nt++)
                    mma_tf32(acc[mt][nt][0], acc[mt][nt][1],
                             acc[mt][nt][2], acc[mt][nt][3],
                             afr[mt][0], afr[mt][1], afr[mt][2], afr[mt][3],
                             bfr[nt][0], bfr[nt][1]);
        }
        buf ^= 1;
    }

    // epilogue
#pragma unroll
    for (int mt = 0; mt < 4; mt++) {
        int row0 = bm + wm + mt * 16 + gid;
#pragma unroll
        for (int nt = 0; nt < 8; nt++) {
            int col = bn + wn + nt * 8 + 2 * tig;
            float bx = bias[col], by = bias[col + 1];
            float2 v0, v1;
            v0.x = acc[mt][nt][0] + bx; v0.y = acc[mt][nt][1] + by;
            v1.x = acc[mt][nt][2] + bx; v1.y = acc[mt][nt][3] + by;
            if (RELU) {
                v0.x = fmaxf(v0.x, 0.f); v0.y = fmaxf(v0.y, 0.f);
                v1.x = fmaxf(v1.x, 0.f); v1.y = fmaxf(v1.y, 0.f);
            }
            *(float2*)&C[(size_t)row0 * N + col]       = v0;
            *(float2*)&C[(size_t)(row0 + 8) * N + col] = v1;
        }
    }
}

// ---------------------------------------------------------------------------
// Tensor-core flash attention (unchanged from R4)
// ---------------------------------------------------------------------------
#define AT_SK 68
#define AT_SV 72
#define AT_SP 68
#define ATTN_SMEM ((64*AT_SK + 64*AT_SV + 64*AT_SP) * 4)   // 53248 bytes

__global__ void __launch_bounds__(128, 3) attn_tc_kernel(
    const float* __restrict__ Qg, const float* __restrict__ Kg,
    const float* __restrict__ Vg, float* __restrict__ Og)
{
    extern __shared__ uint32_t smu[];
    uint32_t* Ks = smu;                  // [64][68] tf32 bits
    uint32_t* Vs = Ks + 64 * AT_SK;      // [64][72] tf32 bits
    uint32_t* Ps = Vs + 64 * AT_SV;      // [64][68]
    float* Qstage = (float*)Ps;

    int tid  = threadIdx.x;
    int warp = tid >> 5, lane = tid & 31;
    int gid  = lane >> 2, tig = lane & 3;
    int wm   = warp * 16;
    int qt = blockIdx.x, h = blockIdx.y, b = blockIdx.z;

    const float* qbase = Qg + (size_t)(b * SEQ + qt * 64) * DM + h * DHD;
#pragma unroll
    for (int i = 0; i < 8; i++) {
        int id  = tid + i * 128;
        int row = id >> 4, c = (id & 15) * 4;
        float4 v = *(const float4*)(qbase + (size_t)row * DM + c);
        float* d = Qstage + row * AT_SP + c;
        d[0] = v.x; d[1] = v.y; d[2] = v.z; d[3] = v.w;
    }
    __syncthreads();

    uint32_t qa[8][4];
#pragma unroll
    for (int ks = 0; ks < 8; ks++) {
        qa[ks][0] = to_tf32(Qstage[(wm + gid)     * AT_SP + ks * 8 + tig]     * 0.125f);
        qa[ks][1] = to_tf32(Qstage[(wm + gid + 8) * AT_SP + ks * 8 + tig]     * 0.125f);
        qa[ks][2] = to_tf32(Qstage[(wm + gid)     * AT_SP + ks * 8 + tig + 4] * 0.125f);
        qa[ks][3] = to_tf32(Qstage[(wm + gid + 8) * AT_SP + ks * 8 + tig + 4] * 0.125f);
    }

    float oa[8][4];
#pragma unroll
    for (int nt = 0; nt < 8; nt++) {
        oa[nt][0] = 0.f; oa[nt][1] = 0.f; oa[nt][2] = 0.f; oa[nt][3] = 0.f;
    }
    float m0 = -1e30f, m1 = -1e30f, l0 = 0.f, l1 = 0.f;

    for (int kt = 0; kt < 16; kt++) {
        __syncthreads();
        const float* kb = Kg + (size_t)(b * SEQ + kt * 64) * DM + h * DHD;
        const float* vb = Vg + (size_t)(b * SEQ + kt * 64) * DM + h * DHD;
#pragma unroll
        for (int i = 0; i < 8; i++) {
            int id  = tid + i * 128;
            int row = id >> 4, c = (id & 15) * 4;
            float4 kv = *(const float4*)(kb + (size_t)row * DM + c);
            float4 vv = *(const float4*)(vb + (size_t)row * DM + c);
            *(uint4*)(Ks + row * AT_SK + c) = cvt4(kv);
            *(uint4*)(Vs + row * AT_SV + c) = cvt4(vv);
        }
        __syncthreads();

        float sc[8][4];
#pragma unroll
        for (int nt = 0; nt < 8; nt++) {
            sc[nt][0] = 0.f; sc[nt][1] = 0.f; sc[nt][2] = 0.f; sc[nt][3] = 0.f;
        }
#pragma unroll
        for (int ks = 0; ks < 8; ks++) {
#pragma unroll
            for (int nt = 0; nt < 8; nt++) {
                uint32_t b0 = Ks[(nt * 8 + gid) * AT_SK + ks * 8 + tig];
                uint32_t b1 = Ks[(nt * 8 + gid) * AT_SK + ks * 8 + tig + 4];
                mma_tf32(sc[nt][0], sc[nt][1], sc[nt][2], sc[nt][3],
                         qa[ks][0], qa[ks][1], qa[ks][2], qa[ks][3], b0, b1);
            }
        }

        float mt0 = -1e30f, mt1 = -1e30f;
#pragma unroll
        for (int nt = 0; nt < 8; nt++) {
            mt0 = fmaxf(mt0, fmaxf(sc[nt][0], sc[nt][1]));
            mt1 = fmaxf(mt1, fmaxf(sc[nt][2], sc[nt][3]));
        }
        mt0 = fmaxf(mt0, __shfl_xor_sync(0xffffffffu, mt0, 1));
        mt0 = fmaxf(mt0, __shfl_xor_sync(0xffffffffu, mt0, 2));
        mt1 = fmaxf(mt1, __shfl_xor_sync(0xffffffffu, mt1, 1));
        mt1 = fmaxf(mt1, __shfl_xor_sync(0xffffffffu, mt1, 2));
        float mn0 = fmaxf(m0, mt0), mn1 = fmaxf(m1, mt1);
        float a0 = __expf(m0 - mn0), a1 = __expf(m1 - mn1);

        float s0 = 0.f, s1 = 0.f;
#pragma unroll
        for (int nt = 0; nt < 8; nt++) {
            sc[nt][0] = __expf(sc[nt][0] - mn0);
            sc[nt][1] = __expf(sc[nt][1] - mn0);
            sc[nt][2] = __expf(sc[nt][2] - mn1);
            sc[nt][3] = __expf(sc[nt][3] - mn1);
            s0 += sc[nt][0] + sc[nt][1];
            s1 += sc[nt][2] + sc[nt][3];
        }
        s0 += __shfl_xor_sync(0xffffffffu, s0, 1);
        s0 += __shfl_xor_sync(0xffffffffu, s0, 2);
        s1 += __shfl_xor_sync(0xffffffffu, s1, 1);
        s1 += __shfl_xor_sync(0xffffffffu, s1, 2);
        l0 = l0 * a0 + s0;
        l1 = l1 * a1 + s1;
#pragma unroll
        for (int nt = 0; nt < 8; nt++) {
            oa[nt][0] *= a0; oa[nt][1] *= a0;
            oa[nt][2] *= a1; oa[nt][3] *= a1;
        }
        m0 = mn0; m1 = mn1;

#pragma unroll
        for (int nt = 0; nt < 8; nt++) {
            uint2 p01; p01.x = to_tf32(sc[nt][0]); p01.y = to_tf32(sc[nt][1]);
            *(uint2*)&Ps[(wm + gid) * AT_SP + nt * 8 + 2 * tig] = p01;
            uint2 p23; p23.x = to_tf32(sc[nt][2]); p23.y = to_tf32(sc[nt][3]);
            *(uint2*)&Ps[(wm + gid + 8) * AT_SP + nt * 8 + 2 * tig] = p23;
        }
        __syncwarp();

#pragma unroll
        for (int ks = 0; ks < 8; ks++) {
            uint32_t pa0 = Ps[(wm + gid)     * AT_SP + ks * 8 + tig];
            uint32_t pa1 = Ps[(wm + gid + 8) * AT_SP + ks * 8 + tig];
            uint32_t pa2 = Ps[(wm + gid)     * AT_SP + ks * 8 + tig + 4];
            uint32_t pa3 = Ps[(wm + gid + 8) * AT_SP + ks * 8 + tig + 4];
#pragma unroll
            for (int nt = 0; nt < 8; nt++) {
                uint32_t b0 = Vs[(ks * 8 + tig)     * AT_SV + nt * 8 + gid];
                uint32_t b1 = Vs[(ks * 8 + tig + 4) * AT_SV + nt * 8 + gid];
                mma_tf32(oa[nt][0], oa[nt][1], oa[nt][2], oa[nt][3],
                         pa0, pa1, pa2, pa3, b0, b1);
            }
        }
    }

    float i0 = 1.f / l0, i1 = 1.f / l1;
    float* ob = Og + (size_t)(b * SEQ + qt * 64) * DM + h * DHD;
#pragma unroll
    for (int nt = 0; nt < 8; nt++) {
        float2 v0; v0.x = oa[nt][0] * i0; v0.y = oa[nt][1] * i0;
        *(float2*)&ob[(size_t)(wm + gid) * DM + nt * 8 + 2 * tig] = v0;
        float2 v1; v1.x = oa[nt][2] * i1; v1.y = oa[nt][3] * i1;
        *(float2*)&ob[(size_t)(wm + gid + 8) * DM + nt * 8 + 2 * tig] = v1;
    }
}

// ---------------------------------------------------------------------------
// Fused residual + LayerNorm — unchanged.
// ---------------------------------------------------------------------------
__global__ void __launch_bounds__(256) ln_kernel(
    const float* __restrict__ Xa, const float* __restrict__ Xb,
    const float* __restrict__ g, const float* __restrict__ beta,
    float* __restrict__ out)
{
    int row = blockIdx.x;
    const float* a = Xa + (size_t)row * DM;
    const float* b = Xb + (size_t)row * DM;
    float vloc[4];
    float s = 0.f, ss = 0.f;
#pragma unroll
    for (int k = 0; k < 4; k++) {
        int i = threadIdx.x + k * 256;
        float v = a[i] + b[i];
        vloc[k] = v; s += v; ss += v * v;
    }
#pragma unroll
    for (int o = 16; o > 0; o >>= 1) {
        s  += __shfl_xor_sync(0xffffffffu, s, o);
        ss += __shfl_xor_sync(0xffffffffu, ss, o);
    }
    __shared__ float red[16];
    __shared__ float mu_s, rstd_s;
    int wid = threadIdx.x >> 5, lid = threadIdx.x & 31;
    if (lid == 0) { red[wid] = s; red[8 + wid] = ss; }
    __syncthreads();
    if (threadIdx.x == 0) {
        float S = 0.f, SS = 0.f;
        for (int i = 0; i < 8; i++) { S += red[i]; SS += red[8 + i]; }
        float mu = S * (1.f / DM);
        float var = SS * (1.f / DM) - mu * mu;
        mu_s = mu;
        rstd_s = rsqrtf(var + 1e-5f);
    }
    __syncthreads();
    float mu = mu_s, rstd = rstd_s;
    float* o = out + (size_t)row * DM;
#pragma unroll
    for (int k = 0; k < 4; k++) {
        int i = threadIdx.x + k * 256;
        o[i] = (vloc[k] - mu) * rstd * g[i] + beta[i];
    }
}

// ---------------------------------------------------------------------------
// Launch
// ---------------------------------------------------------------------------
extern "C" void kernel_launch(void* const* d_in, const int* in_sizes, int n_in,
                              void* d_out, int out_size)
{
    const float* q_in = (const float*)d_in[0];
    const float* mA   = (const float*)d_in[1];
    const float* mB   = (const float*)d_in[2];
    const float* Wq1 = (const float*)d_in[3];  const float* bq1 = (const float*)d_in[4];
    const float* Wk1 = (const float*)d_in[5];  const float* bk1 = (const float*)d_in[6];
    const float* Wv1 = (const float*)d_in[7];  const float* bv1 = (const float*)d_in[8];
    const float* Wo1 = (const float*)d_in[9];  const float* bo1 = (const float*)d_in[10];
    const float* Wq2 = (const float*)d_in[11]; const float* bq2 = (const float*)d_in[12];
    const float* Wk2 = (const float*)d_in[13]; const float* bk2 = (const float*)d_in[14];
    const float* Wv2 = (const float*)d_in[15]; const float* bv2 = (const float*)d_in[16];
    const float* Wo2 = (const float*)d_in[17]; const float* bo2 = (const float*)d_in[18];
    const float* W1  = (const float*)d_in[19]; const float* b1  = (const float*)d_in[20];
    const float* W2  = (const float*)d_in[21]; const float* b2  = (const float*)d_in[22];
    const float* g1  = (const float*)d_in[23]; const float* be1 = (const float*)d_in[24];
    const float* g2  = (const float*)d_in[25]; const float* be2 = (const float*)d_in[26];
    const float* g3  = (const float*)d_in[27]; const float* be3 = (const float*)d_in[28];
    float* out = (float*)d_out;

    float *pQ, *pK, *pV, *pAttn, *pTmp, *pX1, *pX2, *pHid;
    cudaGetSymbolAddress((void**)&pQ,    g_Q);
    cudaGetSymbolAddress((void**)&pK,    g_K);
    cudaGetSymbolAddress((void**)&pV,    g_V);
    cudaGetSymbolAddress((void**)&pAttn, g_Attn);
    cudaGetSymbolAddress((void**)&pTmp,  g_Tmp);
    cudaGetSymbolAddress((void**)&pX1,   g_X1);
    cudaGetSymbolAddress((void**)&pX2,   g_X2);
    cudaGetSymbolAddress((void**)&pHid,  g_Hid);

    cudaFuncSetAttribute(attn_tc_kernel, cudaFuncAttributeMaxDynamicSharedMemorySize, ATTN_SMEM);
    cudaFuncSetAttribute(tc_gemm_kernel<false,false>, cudaFuncAttributeMaxDynamicSharedMemorySize, GEMM_SMEM);
    cudaFuncSetAttribute(tc_gemm_kernel<false,true>,  cudaFuncAttributeMaxDynamicSharedMemorySize, GEMM_SMEM);
    cudaFuncSetAttribute(tc_gemm_kernel<true,false>,  cudaFuncAttributeMaxDynamicSharedMemorySize, GEMM_SMEM);

    const dim3 blk(256);
    const dim3 ablk(128);
    const dim3 gGemm1k(DM / BN, NTOK / BM);          // (4, 32)
    const dim3 gGemmFF1(HIDN / BN, NTOK / BM);       // (16, 32)
    const dim3 gAttn(SEQ / 64, NH, BATCH);
    const dim3 gLN(NTOK);

    // ---- Attention block 1: Q from query, K/V from modality_A ----
    tc_gemm_kernel<false,true><<<gGemm1k, blk, GEMM_SMEM>>>(q_in, Wq1, bq1, pQ, NTOK, DM, DM);
    tc_gemm_kernel<false,true><<<gGemm1k, blk, GEMM_SMEM>>>(mA,   Wk1, bk1, pK, NTOK, DM, DM);
    tc_gemm_kernel<false,true><<<gGemm1k, blk, GEMM_SMEM>>>(mA,   Wv1, bv1, pV, NTOK, DM, DM);
    attn_tc_kernel<<<gAttn, ablk, ATTN_SMEM>>>(pQ, pK, pV, pAttn);
    tc_gemm_kernel<false,false><<<gGemm1k, blk, GEMM_SMEM>>>(pAttn, Wo1, bo1, pTmp, NTOK, DM, DM);
    ln_kernel<<<gLN, blk>>>(q_in, pTmp, g1, be1, pX1);

    // ---- Attention block 2: Q from x1, K/V from modality_B ----
    tc_gemm_kernel<false,true><<<gGemm1k, blk, GEMM_SMEM>>>(pX1, Wq2, bq2, pQ, NTOK, DM, DM);
    tc_gemm_kernel<false,true><<<gGemm1k, blk, GEMM_SMEM>>>(mB,  Wk2, bk2, pK, NTOK, DM, DM);
    tc_gemm_kernel<false,true><<<gGemm1k, blk, GEMM_SMEM>>>(mB,  Wv2, bv2, pV, NTOK, DM, DM);
    attn_tc_kernel<<<gAttn, ablk, ATTN_SMEM>>>(pQ, pK, pV, pAttn);
    tc_gemm_kernel<false,false><<<gGemm1k, blk, GEMM_SMEM>>>(pAttn, Wo2, bo2, pTmp, NTOK, DM, DM);
    ln_kernel<<<gLN, blk>>>(pX1, pTmp, g2, be2, pX2);

    // ---- FFN ----
    tc_gemm_kernel<true,false><<<gGemmFF1, blk, GEMM_SMEM>>>(pX2, W1, b1, pHid, NTOK, HIDN, DM);
    tc_gemm_kernel<false,false><<<gGemm1k, blk, GEMM_SMEM>>>(pHid, W2, b2, pTmp, NTOK, DM, HIDN);
    ln_kernel<<<gLN, blk>>>(pX2, pTmp, g3, be3, out);
}